// round 5
// baseline (speedup 1.0000x reference)
#include <cuda_runtime.h>

// Problem shape (fixed by the benchmark):
//   pred_logits: (16, 900, 92) f32
//   pred_boxes : (16, 900, 4)  f32
//   tgt_labels : (512,)        int32 OR int64 (JAX x64-dependent) -- handled
//   tgt_boxes  : (512, 4)      f32
//   n_targets  : scalar (= 32)
//   output     : (900, 512)    f32  (0/1 assignment)
#define BB 16
#define QQ 900
#define CC 92
#define NP 32
#define TT (BB*NP)

// Scratch: per-block cost matrices, layout [b][t][q]
__device__ float g_cost[(size_t)BB * NP * QQ];
// Normalized labels (int32, clamped to [0, CC-1])
__device__ int g_lab[TT];

// ---------------------------------------------------------------------------
// Normalize labels: detect int32 vs int64 storage, clamp, write g_lab.
// Probes only the first 1024 bytes (in-bounds under both interpretations).
// ---------------------------------------------------------------------------
__global__ void lab_kernel(const int* __restrict__ raw) {
    __shared__ int s_odd_nonzero;
    if (threadIdx.x == 0) s_odd_nonzero = 0;
    __syncthreads();
    if (threadIdx.x < 128) {
        if (raw[2 * threadIdx.x + 1] != 0) atomicOr(&s_odd_nonzero, 1);
    }
    __syncthreads();
    bool is_i64 = (s_odd_nonzero == 0);
    for (int t = threadIdx.x; t < TT; t += blockDim.x) {
        int val = is_i64 ? raw[2 * t] : raw[t];
        val = min(max(val, 0), CC - 1);
        g_lab[t] = val;
    }
}

// ---------------------------------------------------------------------------
__global__ void zero_out_kernel(float* __restrict__ out) {
    int n = QQ * TT;
    for (int i = blockIdx.x * blockDim.x + threadIdx.x; i < n;
         i += gridDim.x * blockDim.x)
        out[i] = 0.0f;
}

// ---------------------------------------------------------------------------
// Build the 16 diagonal cost blocks: cost[b][t][q]
//   cost = 5 * L1(cxcywh) - softmax_prob[label] - 2 * GIoU(xyxy)
// ---------------------------------------------------------------------------
__global__ void cost_kernel(const float* __restrict__ logits,
                            const float* __restrict__ pboxes,
                            const float* __restrict__ tboxes) {
    int b = blockIdx.x;
    __shared__ int    s_lab[NP];
    __shared__ float4 s_tb[NP];    // target cxcywh
    __shared__ float4 s_txy[NP];   // target xyxy
    __shared__ float  s_tarea[NP];

    int tid = threadIdx.x;
    if (tid < NP) {
        int g = b * NP + tid;
        s_lab[tid] = g_lab[g];
        float4 tb = reinterpret_cast<const float4*>(tboxes)[g];
        s_tb[tid] = tb;
        float x0 = tb.x - 0.5f * tb.z, y0 = tb.y - 0.5f * tb.w;
        float x1 = tb.x + 0.5f * tb.z, y1 = tb.y + 0.5f * tb.w;
        s_txy[tid] = make_float4(x0, y0, x1, y1);
        s_tarea[tid] = (x1 - x0) * (y1 - y0);
    }
    __syncthreads();

    int q = blockIdx.y * blockDim.x + tid;
    if (q >= QQ) return;

    const float* lrow = logits + ((size_t)b * QQ + q) * CC;
    float mx = -1e30f;
    #pragma unroll 4
    for (int c = 0; c < CC; c++) mx = fmaxf(mx, lrow[c]);
    float sum = 0.0f;
    #pragma unroll 4
    for (int c = 0; c < CC; c++) sum += expf(lrow[c] - mx);
    float inv = 1.0f / sum;

    float4 pb = reinterpret_cast<const float4*>(pboxes)[b * QQ + q];
    float px0 = pb.x - 0.5f * pb.z, py0 = pb.y - 0.5f * pb.w;
    float px1 = pb.x + 0.5f * pb.z, py1 = pb.y + 0.5f * pb.w;
    float parea = (px1 - px0) * (py1 - py0);

    #pragma unroll 8
    for (int t = 0; t < NP; t++) {
        float prob = expf(lrow[s_lab[t]] - mx) * inv;
        float4 tb = s_tb[t];
        float l1 = fabsf(pb.x - tb.x) + fabsf(pb.y - tb.y) +
                   fabsf(pb.z - tb.z) + fabsf(pb.w - tb.w);
        float4 txy = s_txy[t];
        float ltx = fmaxf(px0, txy.x), lty = fmaxf(py0, txy.y);
        float rbx = fminf(px1, txy.z), rby = fminf(py1, txy.w);
        float wi = fmaxf(rbx - ltx, 0.0f), hi = fmaxf(rby - lty, 0.0f);
        float inter = wi * hi;
        float uni = parea + s_tarea[t] - inter;
        float iou = inter / uni;
        float cx0 = fminf(px0, txy.x), cy0 = fminf(py0, txy.y);
        float cx1 = fmaxf(px1, txy.z), cy1 = fmaxf(py1, txy.w);
        float wc = fmaxf(cx1 - cx0, 0.0f), hc = fmaxf(cy1 - cy0, 0.0f);
        float areac = wc * hc;
        float giou = iou - (areac - uni) / areac;
        float cost = 5.0f * l1 - prob - 2.0f * giou;
        g_cost[((size_t)(b * NP + t)) * QQ + q] = cost;
    }
}

// ---------------------------------------------------------------------------
// Replicates the REFERENCE _lsa exactly, including its quirk: the cur-value
// improvements feed the argmin (via eff = min(cur, minv)) and `way`, but are
// NEVER stored back to minv; minv only decays by delta each iteration.
// fp64 duals, first-index argmin, duals updated before the break check.
// One CTA per batch block (n=32 rows, m=900 cols).
// ---------------------------------------------------------------------------
#define LSA_THREADS 256
#define NWARP (LSA_THREADS/32)

__global__ void lsa_kernel(float* __restrict__ out) {
    __shared__ double minv[QQ + 4];
    __shared__ double v[QQ + 4];
    __shared__ double u[NP + 8];
    __shared__ double wv[NWARP];
    __shared__ int    wj[NWARP];
    __shared__ int    way[QQ + 4];
    __shared__ int    p[QQ + 4];
    __shared__ int    s_j0, s_done;
    __shared__ double s_delta;
    __shared__ unsigned char used[QQ + 4];

    const int tid  = threadIdx.x;
    const int lane = tid & 31;
    const int wid  = tid >> 5;
    const int bd   = LSA_THREADS;
    const int b    = blockIdx.x;
    const double INF = 1e18;

    const float* __restrict__ cs = g_cost + (size_t)b * NP * QQ;

    for (int j = tid; j <= QQ; j += bd) { v[j] = 0.0; p[j] = 0; }
    for (int i = tid; i <= NP; i += bd) u[i] = 0.0;
    __syncthreads();

    for (int i = 1; i <= NP; i++) {
        if (tid == 0) { p[0] = i; s_j0 = 0; s_done = 0; }
        for (int j = tid; j <= QQ; j += bd) { minv[j] = INF; used[j] = 0; }
        __syncthreads();

        while (true) {
            // top of reference loop: used[j0] = True
            if (tid == 0) used[s_j0] = 1;
            __syncthreads();

            const int    j0  = s_j0;
            const int    i0  = p[j0];
            const double ui0 = u[i0];
            const float* crow = cs + (size_t)(i0 - 1) * QQ;

            // scan: eff = (cur < minv) ? cur : minv ; way on strict improve.
            // minv itself is NOT updated here (reference quirk).
            double bestv = INF;
            int    bestj = QQ + 1;
            for (int j = tid + 1; j <= QQ; j += bd) {
                if (!used[j]) {
                    double cur = (double)__ldg(crow + (j - 1)) - ui0 - v[j];
                    double mv  = minv[j];
                    double eff;
                    if (cur < mv) { way[j] = j0; eff = cur; }
                    else          { eff = mv; }
                    if (eff < bestv) { bestv = eff; bestj = j; }
                }
            }
            // warp lexicographic (val, idx)-min
            #pragma unroll
            for (int off = 16; off > 0; off >>= 1) {
                double ov = __shfl_xor_sync(0xffffffffu, bestv, off);
                int    oj = __shfl_xor_sync(0xffffffffu, bestj, off);
                if (ov < bestv || (ov == bestv && oj < bestj)) {
                    bestv = ov; bestj = oj;
                }
            }
            if (lane == 0) { wv[wid] = bestv; wj[wid] = bestj; }
            __syncthreads();

            if (tid == 0) {
                double fv = wv[0]; int fj = wj[0];
                #pragma unroll
                for (int w = 1; w < NWARP; w++) {
                    double ov = wv[w]; int oj = wj[w];
                    if (ov < fv || (ov == fv && oj < fj)) { fv = ov; fj = oj; }
                }
                s_j0 = fj;            // j0 for next iteration
                s_delta = fv;
                s_done = (p[fj] == 0) ? 1 : 0;
            }
            __syncthreads();

            // dual updates (reference order: before the break check).
            // j1 (= s_j0 now) is still unused here -> gets minv decay only.
            const double delta = s_delta;
            for (int j = tid; j <= QQ; j += bd) {
                if (used[j]) { u[p[j]] += delta; v[j] -= delta; }
                else         { minv[j] -= delta; }
            }
            __syncthreads();
            if (s_done) break;
        }

        // augment (serial)
        if (tid == 0) {
            int j0 = s_j0;
            while (j0) { int j1 = way[j0]; p[j0] = p[j1]; j0 = j1; }
        }
        __syncthreads();
    }

    // write result: sol[q, b*32 + t] = 1 where p[q+1]-1 == t
    for (int j = tid + 1; j <= QQ; j += bd) {
        int t = p[j] - 1;
        if (t >= 0) out[(size_t)(j - 1) * TT + b * NP + t] = 1.0f;
    }
}

// ---------------------------------------------------------------------------
extern "C" void kernel_launch(void* const* d_in, const int* in_sizes, int n_in,
                              void* d_out, int out_size) {
    const float* logits = (const float*)d_in[0];
    const float* pboxes = (const float*)d_in[1];
    const int*   labraw = (const int*)d_in[2];
    const float* tboxes = (const float*)d_in[3];
    float* out = (float*)d_out;

    lab_kernel<<<1, 512>>>(labraw);
    zero_out_kernel<<<240, 256>>>(out);
    dim3 g(BB, (QQ + 127) / 128);
    cost_kernel<<<g, 128>>>(logits, pboxes, tboxes);
    lsa_kernel<<<BB, LSA_THREADS>>>(out);
}

// round 6
// speedup vs baseline: 1.1345x; 1.1345x over previous
#include <cuda_runtime.h>

// Problem shape (fixed by the benchmark):
//   pred_logits: (16, 900, 92) f32
//   pred_boxes : (16, 900, 4)  f32
//   tgt_labels : (512,)        int32 OR int64 (JAX x64-dependent) -- handled
//   tgt_boxes  : (512, 4)      f32
//   n_targets  : scalar (= 32)
//   output     : (900, 512)    f32  (0/1 assignment)
#define BB 16
#define QQ 900
#define CC 92
#define NP 32
#define TT (BB*NP)

// Per-block cost matrices, layout [b][t][q], stored as fp64 (exact widening of
// the f32 cost, matching np.asarray(c, dtype=np.float64)).
__device__ double g_cost[(size_t)BB * NP * QQ];
// Normalized labels (int32, clamped to [0, CC-1])
__device__ int g_lab[TT];

// ---------------------------------------------------------------------------
// Normalize labels: detect int32 vs int64 storage, clamp, write g_lab.
// Probes only the first 1024 bytes (in-bounds under both interpretations).
// ---------------------------------------------------------------------------
__global__ void lab_kernel(const int* __restrict__ raw) {
    __shared__ int s_odd_nonzero;
    if (threadIdx.x == 0) s_odd_nonzero = 0;
    __syncthreads();
    if (threadIdx.x < 128) {
        if (raw[2 * threadIdx.x + 1] != 0) atomicOr(&s_odd_nonzero, 1);
    }
    __syncthreads();
    bool is_i64 = (s_odd_nonzero == 0);
    for (int t = threadIdx.x; t < TT; t += blockDim.x) {
        int val = is_i64 ? raw[2 * t] : raw[t];
        val = min(max(val, 0), CC - 1);
        g_lab[t] = val;
    }
}

// ---------------------------------------------------------------------------
// Build the 16 diagonal cost blocks: cost[b][t][q]  (f32 math, f64 store)
//   cost = 5 * L1(cxcywh) - softmax_prob[label] - 2 * GIoU(xyxy)
// ---------------------------------------------------------------------------
__global__ void cost_kernel(const float* __restrict__ logits,
                            const float* __restrict__ pboxes,
                            const float* __restrict__ tboxes) {
    int b = blockIdx.x;
    __shared__ int    s_lab[NP];
    __shared__ float4 s_tb[NP];    // target cxcywh
    __shared__ float4 s_txy[NP];   // target xyxy
    __shared__ float  s_tarea[NP];

    int tid = threadIdx.x;
    if (tid < NP) {
        int g = b * NP + tid;
        s_lab[tid] = g_lab[g];
        float4 tb = reinterpret_cast<const float4*>(tboxes)[g];
        s_tb[tid] = tb;
        float x0 = tb.x - 0.5f * tb.z, y0 = tb.y - 0.5f * tb.w;
        float x1 = tb.x + 0.5f * tb.z, y1 = tb.y + 0.5f * tb.w;
        s_txy[tid] = make_float4(x0, y0, x1, y1);
        s_tarea[tid] = (x1 - x0) * (y1 - y0);
    }
    __syncthreads();

    int q = blockIdx.y * blockDim.x + tid;
    if (q >= QQ) return;

    const float* lrow = logits + ((size_t)b * QQ + q) * CC;
    float mx = -1e30f;
    #pragma unroll 4
    for (int c = 0; c < CC; c++) mx = fmaxf(mx, lrow[c]);
    float sum = 0.0f;
    #pragma unroll 4
    for (int c = 0; c < CC; c++) sum += expf(lrow[c] - mx);
    float inv = 1.0f / sum;

    float4 pb = reinterpret_cast<const float4*>(pboxes)[b * QQ + q];
    float px0 = pb.x - 0.5f * pb.z, py0 = pb.y - 0.5f * pb.w;
    float px1 = pb.x + 0.5f * pb.z, py1 = pb.y + 0.5f * pb.w;
    float parea = (px1 - px0) * (py1 - py0);

    #pragma unroll 8
    for (int t = 0; t < NP; t++) {
        float prob = expf(lrow[s_lab[t]] - mx) * inv;
        float4 tb = s_tb[t];
        float l1 = fabsf(pb.x - tb.x) + fabsf(pb.y - tb.y) +
                   fabsf(pb.z - tb.z) + fabsf(pb.w - tb.w);
        float4 txy = s_txy[t];
        float ltx = fmaxf(px0, txy.x), lty = fmaxf(py0, txy.y);
        float rbx = fminf(px1, txy.z), rby = fminf(py1, txy.w);
        float wi = fmaxf(rbx - ltx, 0.0f), hi = fmaxf(rby - lty, 0.0f);
        float inter = wi * hi;
        float uni = parea + s_tarea[t] - inter;
        float iou = inter / uni;
        float cx0 = fminf(px0, txy.x), cy0 = fminf(py0, txy.y);
        float cx1 = fmaxf(px1, txy.z), cy1 = fmaxf(py1, txy.w);
        float wc = fmaxf(cx1 - cx0, 0.0f), hc = fmaxf(cy1 - cy0, 0.0f);
        float areac = wc * hc;
        float giou = iou - (areac - uni) / areac;
        float cost = 5.0f * l1 - prob - 2.0f * giou;
        g_cost[((size_t)(b * NP + t)) * QQ + q] = (double)cost;
    }
}

// ---------------------------------------------------------------------------
// Reference _lsa, degenerate-form-exact. Key facts (provable at these
// magnitudes): minv is never assigned cur in the reference, so all unused
// columns share minv = 1e18 - sum(delta) and cur < minv ALWAYS. Hence:
//   * eff = cur; way[j] = j0 for every unused j -> augmenting path == pivot
//     chain; minv bookkeeping is decision-irrelevant and dropped.
//   * dual updates touch only chain columns/rows (O(L) per iteration).
// cur = (c[i0-1][j] - u[i0]) - v[j] computed in fp64, left-to-right, exactly
// as the reference. First-index argmin via lexicographic (val, idx) min.
// One CTA per batch block. 2 __syncthreads per inner iteration.
// ---------------------------------------------------------------------------
#define LSA_THREADS 128
#define NWARP (LSA_THREADS/32)

__global__ void lsa_kernel(float* __restrict__ out) {
    __shared__ double vv[QQ + 1];      // scan copy of v; -1e30 marks used
    __shared__ double v [QQ + 1];      // true dual v
    __shared__ double u [NP + 2];      // dual u (rows 1..32)
    __shared__ double wv[NWARP];
    __shared__ int    wj[NWARP];
    __shared__ int    p [QQ + 1];      // column -> row (1-based; 0 = free)
    __shared__ int    chain_col[NP + 2];
    __shared__ int    s_j0, s_done, s_L;

    const int tid  = threadIdx.x;
    const int lane = tid & 31;
    const int wid  = tid >> 5;
    const int bd   = LSA_THREADS;
    const int b    = blockIdx.x;

    const double* __restrict__ cs = g_cost + (size_t)b * NP * QQ;

    for (int j = tid; j <= QQ; j += bd) { v[j] = 0.0; vv[j] = 0.0; p[j] = 0; }
    for (int i = tid; i <= NP; i += bd) u[i] = 0.0;
    __syncthreads();

    for (int i = 1; i <= NP; i++) {
        if (tid == 0) {
            p[0] = i;
            chain_col[0] = 0;   // virtual column 0 holds row i
            s_L = 1;
            s_j0 = 0;
            s_done = 0;
        }
        __syncthreads();

        while (true) {
            const int    i0  = p[s_j0];
            const double ui0 = u[i0];
            const double* crow = cs + (size_t)(i0 - 1) * QQ;

            // argmin over unused of cur = (c - u[i0]) - v[j]
            // (used columns have vv = -1e30 -> cur ~ +1e30, never selected)
            double bestv = 1e300;
            int    bestj = QQ + 1;
            for (int j = tid + 1; j <= QQ; j += bd) {
                double cur = (__ldg(crow + (j - 1)) - ui0) - vv[j];
                if (cur < bestv) { bestv = cur; bestj = j; }
            }
            #pragma unroll
            for (int off = 16; off > 0; off >>= 1) {
                double ov = __shfl_xor_sync(0xffffffffu, bestv, off);
                int    oj = __shfl_xor_sync(0xffffffffu, bestj, off);
                if (ov < bestv || (ov == bestv && oj < bestj)) {
                    bestv = ov; bestj = oj;
                }
            }
            if (lane == 0) { wv[wid] = bestv; wj[wid] = bestj; }
            __syncthreads();

            if (tid == 0) {
                double fv = wv[0]; int fj = wj[0];
                #pragma unroll
                for (int w = 1; w < NWARP; w++) {
                    double ov = wv[w]; int oj = wj[w];
                    if (ov < fv || (ov == fv && oj < fj)) { fv = ov; fj = oj; }
                }
                const double delta = fv;
                const int L = s_L;
                // dual update over used set (chain; j1 not yet included)
                for (int k = 0; k < L; k++) {
                    int col = chain_col[k];
                    u[p[col]] += delta;
                    if (col) v[col] -= delta;   // v[0] never read; skip
                }
                // append pivot j1 (== reference's used[j0]=True next iter)
                vv[fj] = -1e30;
                chain_col[L] = fj;
                s_L = L + 1;
                s_j0 = fj;
                s_done = (p[fj] == 0) ? 1 : 0;
            }
            __syncthreads();
            if (s_done) break;
        }

        // augment along pivot chain + restore vv for this phase's used cols
        if (tid == 0) {
            const int L = s_L;
            for (int k = L - 1; k >= 1; k--)
                p[chain_col[k]] = p[chain_col[k - 1]];
            for (int k = 1; k < L; k++)
                vv[chain_col[k]] = v[chain_col[k]];
        }
        __syncthreads();
    }

    // write this block's 32-column output stripe (zeros + assignment ones)
    for (int j = tid + 1; j <= QQ; j += bd) {
        int t = p[j] - 1;
        float4* dst = reinterpret_cast<float4*>(
            out + (size_t)(j - 1) * TT + b * NP);
        #pragma unroll
        for (int k = 0; k < NP / 4; k++) {
            float4 w = make_float4(0.f, 0.f, 0.f, 0.f);
            if (t >= 4 * k && t < 4 * k + 4)
                reinterpret_cast<float*>(&w)[t - 4 * k] = 1.0f;
            dst[k] = w;
        }
    }
}

// ---------------------------------------------------------------------------
extern "C" void kernel_launch(void* const* d_in, const int* in_sizes, int n_in,
                              void* d_out, int out_size) {
    const float* logits = (const float*)d_in[0];
    const float* pboxes = (const float*)d_in[1];
    const int*   labraw = (const int*)d_in[2];
    const float* tboxes = (const float*)d_in[3];
    float* out = (float*)d_out;

    lab_kernel<<<1, 512>>>(labraw);
    dim3 g(BB, (QQ + 127) / 128);
    cost_kernel<<<g, 128>>>(logits, pboxes, tboxes);
    lsa_kernel<<<BB, LSA_THREADS>>>(out);
}

// round 9
// speedup vs baseline: 1.1942x; 1.0527x over previous
#include <cuda_runtime.h>

// Problem shape (fixed by the benchmark):
//   pred_logits: (16, 900, 92) f32
//   pred_boxes : (16, 900, 4)  f32
//   tgt_labels : (512,)        int32 OR int64 (JAX x64-dependent) -- handled
//   tgt_boxes  : (512, 4)      f32
//   n_targets  : scalar (= 32)
//   output     : (900, 512)    f32  (0/1 assignment)
#define BB 16
#define QQ 900
#define CC 92
#define NP 32
#define TT (BB*NP)

// Per-block cost matrices, layout [b][t][q], fp32 (115KB/block -> L1-resident
// during the solve; widened to fp64 exactly at use, matching np.asarray(f64)).
__device__ float g_cost[(size_t)BB * NP * QQ];

// ---------------------------------------------------------------------------
// Build the 16 diagonal cost blocks: cost[b][t][q]
//   cost = 5 * L1(cxcywh) - softmax_prob[label] - 2 * GIoU(xyxy)
// Label dtype (int32 vs int64) detected per-block from the first 1024 bytes
// (in-bounds under both interpretations; labels < 92 so int64 high words = 0).
// ---------------------------------------------------------------------------
__global__ void cost_kernel(const float* __restrict__ logits,
                            const float* __restrict__ pboxes,
                            const int*   __restrict__ labraw,
                            const float* __restrict__ tboxes) {
    int b = blockIdx.x;
    __shared__ int    s_nz;
    __shared__ int    s_lab[NP];
    __shared__ float4 s_tb[NP];    // target cxcywh
    __shared__ float4 s_txy[NP];   // target xyxy
    __shared__ float  s_tarea[NP];

    int tid = threadIdx.x;
    if (tid == 0) s_nz = 0;
    __syncthreads();
    if (labraw[2 * tid + 1] != 0) atomicOr(&s_nz, 1);   // tid < 128
    __syncthreads();
    bool is_i64 = (s_nz == 0);

    if (tid < NP) {
        int g = b * NP + tid;
        int val = is_i64 ? labraw[2 * g] : labraw[g];
        s_lab[tid] = min(max(val, 0), CC - 1);
        float4 tb = reinterpret_cast<const float4*>(tboxes)[g];
        s_tb[tid] = tb;
        float x0 = tb.x - 0.5f * tb.z, y0 = tb.y - 0.5f * tb.w;
        float x1 = tb.x + 0.5f * tb.z, y1 = tb.y + 0.5f * tb.w;
        s_txy[tid] = make_float4(x0, y0, x1, y1);
        s_tarea[tid] = (x1 - x0) * (y1 - y0);
    }
    __syncthreads();

    int q = blockIdx.y * blockDim.x + tid;
    if (q >= QQ) return;

    const float* lrow = logits + ((size_t)b * QQ + q) * CC;
    float mx = -1e30f;
    #pragma unroll 4
    for (int c = 0; c < CC; c++) mx = fmaxf(mx, lrow[c]);
    float sum = 0.0f;
    #pragma unroll 4
    for (int c = 0; c < CC; c++) sum += expf(lrow[c] - mx);
    float inv = 1.0f / sum;

    float4 pb = reinterpret_cast<const float4*>(pboxes)[b * QQ + q];
    float px0 = pb.x - 0.5f * pb.z, py0 = pb.y - 0.5f * pb.w;
    float px1 = pb.x + 0.5f * pb.z, py1 = pb.y + 0.5f * pb.w;
    float parea = (px1 - px0) * (py1 - py0);

    #pragma unroll 8
    for (int t = 0; t < NP; t++) {
        float prob = expf(lrow[s_lab[t]] - mx) * inv;
        float4 tb = s_tb[t];
        float l1 = fabsf(pb.x - tb.x) + fabsf(pb.y - tb.y) +
                   fabsf(pb.z - tb.z) + fabsf(pb.w - tb.w);
        float4 txy = s_txy[t];
        float ltx = fmaxf(px0, txy.x), lty = fmaxf(py0, txy.y);
        float rbx = fminf(px1, txy.z), rby = fminf(py1, txy.w);
        float wi = fmaxf(rbx - ltx, 0.0f), hi = fmaxf(rby - lty, 0.0f);
        float inter = wi * hi;
        float uni = parea + s_tarea[t] - inter;
        float iou = inter / uni;
        float cx0 = fminf(px0, txy.x), cy0 = fminf(py0, txy.y);
        float cx1 = fmaxf(px1, txy.z), cy1 = fmaxf(py1, txy.w);
        float wc = fmaxf(cx1 - cx0, 0.0f), hc = fmaxf(cy1 - cy0, 0.0f);
        float areac = wc * hc;
        float giou = iou - (areac - uni) / areac;
        float cost = 5.0f * l1 - prob - 2.0f * giou;
        g_cost[((size_t)(b * NP + t)) * QQ + q] = cost;
    }
}

// ---------------------------------------------------------------------------
// Reference _lsa, degenerate-form-exact (see round-5/6 analysis):
//   * minv is never written back in the reference, so cur < minv always ->
//     eff = cur, way = pivot chain; minv bookkeeping decision-irrelevant.
//   * dual updates touch only the chain (a matching -> race-free in parallel).
// cur = ((double)c - u[i0]) - v[j], fp64, same order as reference.
// First-index argmin via lexicographic (val, idx) min.
// Per-iteration serial work eliminated: final reduce + chain update + pivot
// bookkeeping all run inside warp 0 (parallel over lanes), 2 barriers/iter.
// ---------------------------------------------------------------------------
#define LSA_THREADS 128
#define NWARP (LSA_THREADS/32)

__global__ void lsa_kernel(float* __restrict__ out) {
    __shared__ double vv[QQ + 1];      // scan copy of v; -1e30 marks used
    __shared__ double v [QQ + 1];      // true dual v
    __shared__ double u [NP + 2];      // dual u (rows 1..32)
    __shared__ double wv[NWARP];
    __shared__ int    wj[NWARP];
    __shared__ int    p [QQ + 1];      // column -> row (1-based; 0 = free)
    __shared__ int    chain_col[NP + 4];
    __shared__ int    s_j0, s_done, s_L;

    const int tid  = threadIdx.x;
    const int lane = tid & 31;
    const int wid  = tid >> 5;
    const int bd   = LSA_THREADS;
    const int b    = blockIdx.x;

    const float* __restrict__ cs = g_cost + (size_t)b * NP * QQ;

    for (int j = tid; j <= QQ; j += bd) { v[j] = 0.0; vv[j] = 0.0; p[j] = 0; }
    for (int i = tid; i <= NP; i += bd) u[i] = 0.0;
    __syncthreads();

    for (int i = 1; i <= NP; i++) {
        if (tid == 0) {
            p[0] = i;
            chain_col[0] = 0;   // virtual column 0 holds row i
            s_L = 1;
            s_j0 = 0;
            s_done = 0;
        }
        __syncthreads();

        while (true) {
            const int    i0  = p[s_j0];
            const double ui0 = u[i0];
            const float* crow = cs + (size_t)(i0 - 1) * QQ;

            // argmin over unused of cur = ((double)c - u[i0]) - v[j]
            // (used columns have vv = -1e30 -> cur ~ +1e30, never selected)
            double bestv = 1e300;
            int    bestj = QQ + 1;
            #pragma unroll 4
            for (int j = tid + 1; j <= QQ; j += bd) {
                double cur = ((double)__ldg(crow + (j - 1)) - ui0) - vv[j];
                if (cur < bestv) { bestv = cur; bestj = j; }
            }
            #pragma unroll
            for (int off = 16; off > 0; off >>= 1) {
                double ov = __shfl_xor_sync(0xffffffffu, bestv, off);
                int    oj = __shfl_xor_sync(0xffffffffu, bestj, off);
                if (ov < bestv || (ov == bestv && oj < bestj)) {
                    bestv = ov; bestj = oj;
                }
            }
            if (lane == 0) { wv[wid] = bestv; wj[wid] = bestj; }
            __syncthreads();

            // warp 0: final reduce + parallel chain dual update + bookkeeping
            if (wid == 0) {
                double fv = 1e300; int fj = QQ + 1;
                if (lane < NWARP) { fv = wv[lane]; fj = wj[lane]; }
                #pragma unroll
                for (int off = NWARP / 2; off > 0; off >>= 1) {
                    double ov = __shfl_xor_sync(0xffffffffu, fv, off);
                    int    oj = __shfl_xor_sync(0xffffffffu, fj, off);
                    if (ov < fv || (ov == fv && oj < fj)) { fv = ov; fj = oj; }
                }
                const double delta = __shfl_sync(0xffffffffu, fv, 0);
                fj = __shfl_sync(0xffffffffu, fj, 0);
                const int L = s_L;
                // dual update over used set (chain; fj not yet included).
                // chain cols/rows are distinct -> race-free.
                for (int k = lane; k < L; k += 32) {
                    int col = chain_col[k];
                    u[p[col]] += delta;
                    if (col) v[col] -= delta;   // v[0] never read; skip
                }
                __syncwarp();
                if (lane == 0) {
                    vv[fj] = -1e30;
                    chain_col[L] = fj;
                    s_L = L + 1;
                    s_j0 = fj;
                    s_done = (p[fj] == 0) ? 1 : 0;
                }
            }
            __syncthreads();
            if (s_done) break;
        }

        // augment along pivot chain + restore vv for this phase's used cols
        if (wid == 0) {
            const int L = s_L;
            int op = 0;
            if (lane >= 1 && lane < L) op = p[chain_col[lane - 1]];
            __syncwarp();
            if (lane >= 1 && lane < L) {
                int col = chain_col[lane];
                p[col] = op;
                vv[col] = v[col];
            }
            // L can be 33 (lane range only covers 1..32): handle k=32 extra
            if (L > 33 - 1 + 1) { /* unreachable: L <= 33 */ }
            if (lane == 0 && L == 34) { /* never happens */ }
        }
        __syncthreads();
    }

    // write this block's 32-column output stripe (zeros + assignment ones)
    for (int j = tid + 1; j <= QQ; j += bd) {
        int t = p[j] - 1;
        float4* dst = reinterpret_cast<float4*>(
            out + (size_t)(j - 1) * TT + b * NP);
        #pragma unroll
        for (int k = 0; k < NP / 4; k++) {
            float4 w = make_float4(0.f, 0.f, 0.f, 0.f);
            if (t >= 4 * k && t < 4 * k + 4)
                reinterpret_cast<float*>(&w)[t - 4 * k] = 1.0f;
            dst[k] = w;
        }
    }
}

// ---------------------------------------------------------------------------
extern "C" void kernel_launch(void* const* d_in, const int* in_sizes, int n_in,
                              void* d_out, int out_size) {
    const float* logits = (const float*)d_in[0];
    const float* pboxes = (const float*)d_in[1];
    const int*   labraw = (const int*)d_in[2];
    const float* tboxes = (const float*)d_in[3];
    float* out = (float*)d_out;

    dim3 g(BB, (QQ + 127) / 128);
    cost_kernel<<<g, 128>>>(logits, pboxes, labraw, tboxes);
    lsa_kernel<<<BB, LSA_THREADS>>>(out);
}

// round 10
// speedup vs baseline: 1.8620x; 1.5591x over previous
#include <cuda_runtime.h>

// Problem shape (fixed by the benchmark):
//   pred_logits: (16, 900, 92) f32
//   pred_boxes : (16, 900, 4)  f32
//   tgt_labels : (512,)        int32 OR int64 (JAX x64-dependent) -- handled
//   tgt_boxes  : (512, 4)      f32
//   n_targets  : scalar (= 32)
//   output     : (900, 512)    f32  (0/1 assignment)
#define BB 16
#define QQ 900
#define CC 92
#define NP 32
#define TT (BB*NP)

// Per-block cost matrices, layout [b][t][q], fp32; widened to fp64 exactly at
// use (matches np.asarray(c, float64)).
__device__ float g_cost[(size_t)BB * NP * QQ];

// ---------------------------------------------------------------------------
// Build the 16 diagonal cost blocks: cost[b][t][q]
//   cost = 5 * L1(cxcywh) - softmax_prob[label] - 2 * GIoU(xyxy)
// Label dtype (int32 vs int64) detected per-block from the first 1024 bytes
// (in-bounds under both interpretations; labels < 92 so int64 high words = 0).
// ---------------------------------------------------------------------------
__global__ void cost_kernel(const float* __restrict__ logits,
                            const float* __restrict__ pboxes,
                            const int*   __restrict__ labraw,
                            const float* __restrict__ tboxes) {
    int b = blockIdx.x;
    __shared__ int    s_nz;
    __shared__ int    s_lab[NP];
    __shared__ float4 s_tb[NP];
    __shared__ float4 s_txy[NP];
    __shared__ float  s_tarea[NP];

    int tid = threadIdx.x;
    if (tid == 0) s_nz = 0;
    __syncthreads();
    if (labraw[2 * tid + 1] != 0) atomicOr(&s_nz, 1);   // tid < 128
    __syncthreads();
    bool is_i64 = (s_nz == 0);

    if (tid < NP) {
        int g = b * NP + tid;
        int val = is_i64 ? labraw[2 * g] : labraw[g];
        s_lab[tid] = min(max(val, 0), CC - 1);
        float4 tb = reinterpret_cast<const float4*>(tboxes)[g];
        s_tb[tid] = tb;
        float x0 = tb.x - 0.5f * tb.z, y0 = tb.y - 0.5f * tb.w;
        float x1 = tb.x + 0.5f * tb.z, y1 = tb.y + 0.5f * tb.w;
        s_txy[tid] = make_float4(x0, y0, x1, y1);
        s_tarea[tid] = (x1 - x0) * (y1 - y0);
    }
    __syncthreads();

    int q = blockIdx.y * blockDim.x + tid;
    if (q >= QQ) return;

    const float* lrow = logits + ((size_t)b * QQ + q) * CC;
    float mx = -1e30f;
    #pragma unroll 4
    for (int c = 0; c < CC; c++) mx = fmaxf(mx, lrow[c]);
    float sum = 0.0f;
    #pragma unroll 4
    for (int c = 0; c < CC; c++) sum += expf(lrow[c] - mx);
    float inv = 1.0f / sum;

    float4 pb = reinterpret_cast<const float4*>(pboxes)[b * QQ + q];
    float px0 = pb.x - 0.5f * pb.z, py0 = pb.y - 0.5f * pb.w;
    float px1 = pb.x + 0.5f * pb.z, py1 = pb.y + 0.5f * pb.w;
    float parea = (px1 - px0) * (py1 - py0);

    #pragma unroll 8
    for (int t = 0; t < NP; t++) {
        float prob = expf(lrow[s_lab[t]] - mx) * inv;
        float4 tb = s_tb[t];
        float l1 = fabsf(pb.x - tb.x) + fabsf(pb.y - tb.y) +
                   fabsf(pb.z - tb.z) + fabsf(pb.w - tb.w);
        float4 txy = s_txy[t];
        float ltx = fmaxf(px0, txy.x), lty = fmaxf(py0, txy.y);
        float rbx = fminf(px1, txy.z), rby = fminf(py1, txy.w);
        float wi = fmaxf(rbx - ltx, 0.0f), hi = fmaxf(rby - lty, 0.0f);
        float inter = wi * hi;
        float uni = parea + s_tarea[t] - inter;
        float iou = inter / uni;
        float cx0 = fminf(px0, txy.x), cy0 = fminf(py0, txy.y);
        float cx1 = fmaxf(px1, txy.z), cy1 = fmaxf(py1, txy.w);
        float wc = fmaxf(cx1 - cx0, 0.0f), hc = fmaxf(cy1 - cy0, 0.0f);
        float areac = wc * hc;
        float giou = iou - (areac - uni) / areac;
        float cost = 5.0f * l1 - prob - 2.0f * giou;
        g_cost[((size_t)(b * NP + t)) * QQ + q] = cost;
    }
}

// ---------------------------------------------------------------------------
// Reference _lsa, degenerate-form-exact (rounds 5-9 analysis). New this round:
// fp32-filtered exact argmin. The 900-wide scan runs in fp32 (B300 fp64 rt is
// 18.4 cyc/SM -> fp64 scan was the bottleneck); candidates within a provably
// safe margin of each warp's fp32 min are re-evaluated in fp64 with the exact
// reference expression, so every decision (delta, pivot, first-index
// tie-break) is bit-identical to the previous passing kernel.
// ---------------------------------------------------------------------------
#define LSA_THREADS 128
#define NWARP (LSA_THREADS/32)
#define NE 8          // max elements per thread: ceil(900/128)

__device__ __forceinline__ int f32_key(float f) {
    int k = __float_as_int(f);
    return k ^ ((k >> 31) & 0x7fffffff);   // monotone signed-int key
}
__device__ __forceinline__ float f32_unkey(int k) {
    return __int_as_float(k ^ ((k >> 31) & 0x7fffffff));
}

__global__ void lsa_kernel(float* __restrict__ out) {
    __shared__ double vv[QQ + 1];      // exact-scan copy of v; -1e30 = used
    __shared__ float  vf[QQ + 1];      // fp32 mirror of vv
    __shared__ double v [QQ + 1];      // true dual v
    __shared__ double u [NP + 2];      // dual u (rows 1..32)
    __shared__ int    p [QQ + 1];      // column -> row (1-based; 0 = free)
    __shared__ int    chain_col[NP + 4];
    __shared__ int    cand[QQ + 4];    // candidate column list
    __shared__ int    s_n;             // candidate count
    __shared__ int    s_j0, s_done, s_L;

    const int tid  = threadIdx.x;
    const int lane = tid & 31;
    const int wid  = tid >> 5;
    const int b    = blockIdx.x;

    const float* __restrict__ cs = g_cost + (size_t)b * NP * QQ;

    for (int j = tid; j <= QQ; j += LSA_THREADS) {
        v[j] = 0.0; vv[j] = 0.0; vf[j] = 0.0f; p[j] = 0;
    }
    for (int i = tid; i <= NP; i += LSA_THREADS) u[i] = 0.0;
    if (tid == 0) s_n = 0;
    __syncthreads();

    for (int i = 1; i <= NP; i++) {
        if (tid == 0) {
            p[0] = i;
            chain_col[0] = 0;   // virtual column 0 holds row i
            s_L = 1;
            s_j0 = 0;
            s_done = 0;
        }
        __syncthreads();

        while (true) {
            const int    i0   = p[s_j0];
            const double ui0d = u[i0];
            const float  ui0f = (float)ui0d;
            const float* crow = cs + (size_t)(i0 - 1) * QQ;

            // ---- fp32 scan: curf = (c - uf) - vf[j]; used cols have
            // vf = -1e30f -> curf huge, never competitive.
            float c8[NE];
            float bestf = 1e30f;
            #pragma unroll
            for (int k = 0; k < NE; k++) {
                int j = tid + 1 + k * LSA_THREADS;
                float cf = 1e30f;
                if (j <= QQ)
                    cf = (__ldg(crow + (j - 1)) - ui0f) - vf[j];
                c8[k] = cf;
                bestf = fminf(bestf, cf);
            }
            // warp fp32 min via hardware redux
            int wmink = __reduce_min_sync(0xffffffffu, f32_key(bestf));
            float minf = f32_unkey(wmink);
            // safe margin: fp32 path error << 1e-2 at these magnitudes
            float thresh = minf + fmaxf(1e-2f, 1e-5f * fabsf(minf));

            // ---- push flagged candidates
            #pragma unroll
            for (int k = 0; k < NE; k++) {
                if (c8[k] <= thresh) {
                    int j = tid + 1 + k * LSA_THREADS;
                    int slot = atomicAdd(&s_n, 1);
                    cand[slot] = j;
                }
            }
            __syncthreads();

            // ---- warp 0: exact fp64 eval of candidates + argmin + duals
            if (wid == 0) {
                const int n = s_n;
                double bestv = 1e300;
                int    bestj = QQ + 1;
                for (int base = 0; base < n; base += 32) {
                    int idx = base + lane;
                    if (idx < n) {
                        int jj = cand[idx];
                        // EXACT reference expression (same as prior kernel)
                        double cur = ((double)__ldg(crow + (jj - 1)) - ui0d)
                                     - vv[jj];
                        if (cur < bestv || (cur == bestv && jj < bestj)) {
                            bestv = cur; bestj = jj;
                        }
                    }
                }
                // lexicographic (val, idx) warp argmin via redux cascade
                long long sbits = __double_as_longlong(bestv);
                unsigned long long ukey = (sbits >= 0)
                    ? ((unsigned long long)sbits | 0x8000000000000000ULL)
                    : ~(unsigned long long)sbits;
                unsigned hi = (unsigned)(ukey >> 32);
                unsigned lo = (unsigned)ukey;
                unsigned hmin = __reduce_min_sync(0xffffffffu, hi);
                unsigned lmin = __reduce_min_sync(0xffffffffu,
                                    (hi == hmin) ? lo : 0xffffffffu);
                int jmin = __reduce_min_sync(0xffffffffu,
                                (hi == hmin && lo == lmin) ? bestj
                                                           : 0x7fffffff);
                unsigned long long ukmin =
                    ((unsigned long long)hmin << 32) | lmin;
                long long rbits = (ukmin & 0x8000000000000000ULL)
                    ? (long long)(ukmin ^ 0x8000000000000000ULL)
                    : ~(long long)ukmin;
                const double delta = __longlong_as_double(rbits);
                const int fj = jmin;

                // dual update over chain (cols/rows distinct -> race-free).
                // vf stays -1e30f for used cols (scan-exclusion mirror of vv).
                const int L = s_L;
                for (int k = lane; k < L; k += 32) {
                    int col = chain_col[k];
                    u[p[col]] += delta;
                    if (col) v[col] -= delta;   // v[0] never read
                }
                __syncwarp();
                if (lane == 0) {
                    vv[fj] = -1e30;
                    vf[fj] = -1e30f;
                    chain_col[L] = fj;
                    s_L = L + 1;
                    s_j0 = fj;
                    s_n = 0;
                    s_done = (p[fj] == 0) ? 1 : 0;
                }
            }
            __syncthreads();
            if (s_done) break;
        }

        // augment along pivot chain + restore vv/vf for this phase's used
        // cols. Chain items m = 1..L-1 (L <= 33 -> exactly lanes 0..31 via
        // m = lane + 1). Read all p's before any write (RAW across lanes).
        if (wid == 0) {
            const int L = s_L;
            const int m = lane + 1;
            int op = 0;
            if (m < L) op = p[chain_col[m - 1]];
            __syncwarp();
            if (m < L) {
                int col = chain_col[m];
                p[col]  = op;
                vv[col] = v[col];
                vf[col] = (float)v[col];
            }
        }
        __syncthreads();
    }

    // write this block's 32-column output stripe (zeros + assignment ones)
    for (int j = tid + 1; j <= QQ; j += LSA_THREADS) {
        int t = p[j] - 1;
        float4* dst = reinterpret_cast<float4*>(
            out + (size_t)(j - 1) * TT + b * NP);
        #pragma unroll
        for (int k = 0; k < NP / 4; k++) {
            float4 w = make_float4(0.f, 0.f, 0.f, 0.f);
            if (t >= 4 * k && t < 4 * k + 4)
                reinterpret_cast<float*>(&w)[t - 4 * k] = 1.0f;
            dst[k] = w;
        }
    }
}

// ---------------------------------------------------------------------------
extern "C" void kernel_launch(void* const* d_in, const int* in_sizes, int n_in,
                              void* d_out, int out_size) {
    const float* logits = (const float*)d_in[0];
    const float* pboxes = (const float*)d_in[1];
    const int*   labraw = (const int*)d_in[2];
    const float* tboxes = (const float*)d_in[3];
    float* out = (float*)d_out;

    dim3 g(BB, (QQ + 127) / 128);
    cost_kernel<<<g, 128>>>(logits, pboxes, labraw, tboxes);
    lsa_kernel<<<BB, LSA_THREADS>>>(out);
}

// round 11
// speedup vs baseline: 2.4175x; 1.2984x over previous
#include <cuda_runtime.h>

// Problem shape (fixed by the benchmark):
//   pred_logits: (16, 900, 92) f32
//   pred_boxes : (16, 900, 4)  f32
//   tgt_labels : (512,)        int32 OR int64 (JAX x64-dependent) -- handled
//   tgt_boxes  : (512, 4)      f32
//   n_targets  : scalar (= 32)
//   output     : (900, 512)    f32  (0/1 assignment)
#define BB 16
#define QQ 900
#define CC 92
#define NP 32
#define TT (BB*NP)

// Per-block cost matrices, layout [b][t][q], fp32; widened to fp64 exactly at
// use (matches np.asarray(c, float64)).
__device__ float g_cost[(size_t)BB * NP * QQ];

// ---------------------------------------------------------------------------
// Build the 16 diagonal cost blocks: cost[b][t][q]
//   cost = 5 * L1(cxcywh) - softmax_prob[label] - 2 * GIoU(xyxy)
// Label dtype (int32 vs int64) detected per-block from the first 1024 bytes
// (in-bounds under both interpretations; labels < 92 so int64 high words = 0).
// ---------------------------------------------------------------------------
__global__ void cost_kernel(const float* __restrict__ logits,
                            const float* __restrict__ pboxes,
                            const int*   __restrict__ labraw,
                            const float* __restrict__ tboxes) {
    int b = blockIdx.x;
    __shared__ int    s_nz;
    __shared__ int    s_lab[NP];
    __shared__ float4 s_tb[NP];
    __shared__ float4 s_txy[NP];
    __shared__ float  s_tarea[NP];

    int tid = threadIdx.x;
    if (tid == 0) s_nz = 0;
    __syncthreads();
    if (labraw[2 * tid + 1] != 0) atomicOr(&s_nz, 1);   // tid < 128
    __syncthreads();
    bool is_i64 = (s_nz == 0);

    if (tid < NP) {
        int g = b * NP + tid;
        int val = is_i64 ? labraw[2 * g] : labraw[g];
        s_lab[tid] = min(max(val, 0), CC - 1);
        float4 tb = reinterpret_cast<const float4*>(tboxes)[g];
        s_tb[tid] = tb;
        float x0 = tb.x - 0.5f * tb.z, y0 = tb.y - 0.5f * tb.w;
        float x1 = tb.x + 0.5f * tb.z, y1 = tb.y + 0.5f * tb.w;
        s_txy[tid] = make_float4(x0, y0, x1, y1);
        s_tarea[tid] = (x1 - x0) * (y1 - y0);
    }
    __syncthreads();

    int q = blockIdx.y * blockDim.x + tid;
    if (q >= QQ) return;

    const float* lrow = logits + ((size_t)b * QQ + q) * CC;
    float mx = -1e30f;
    #pragma unroll 4
    for (int c = 0; c < CC; c++) mx = fmaxf(mx, lrow[c]);
    float sum = 0.0f;
    #pragma unroll 4
    for (int c = 0; c < CC; c++) sum += expf(lrow[c] - mx);
    float inv = 1.0f / sum;

    float4 pb = reinterpret_cast<const float4*>(pboxes)[b * QQ + q];
    float px0 = pb.x - 0.5f * pb.z, py0 = pb.y - 0.5f * pb.w;
    float px1 = pb.x + 0.5f * pb.z, py1 = pb.y + 0.5f * pb.w;
    float parea = (px1 - px0) * (py1 - py0);

    #pragma unroll 8
    for (int t = 0; t < NP; t++) {
        float prob = expf(lrow[s_lab[t]] - mx) * inv;
        float4 tb = s_tb[t];
        float l1 = fabsf(pb.x - tb.x) + fabsf(pb.y - tb.y) +
                   fabsf(pb.z - tb.z) + fabsf(pb.w - tb.w);
        float4 txy = s_txy[t];
        float ltx = fmaxf(px0, txy.x), lty = fmaxf(py0, txy.y);
        float rbx = fminf(px1, txy.z), rby = fminf(py1, txy.w);
        float wi = fmaxf(rbx - ltx, 0.0f), hi = fmaxf(rby - lty, 0.0f);
        float inter = wi * hi;
        float uni = parea + s_tarea[t] - inter;
        float iou = inter / uni;
        float cx0 = fminf(px0, txy.x), cy0 = fminf(py0, txy.y);
        float cx1 = fmaxf(px1, txy.z), cy1 = fmaxf(py1, txy.w);
        float wc = fmaxf(cx1 - cx0, 0.0f), hc = fmaxf(cy1 - cy0, 0.0f);
        float areac = wc * hc;
        float giou = iou - (areac - uni) / areac;
        float cost = 5.0f * l1 - prob - 2.0f * giou;
        g_cost[((size_t)(b * NP + t)) * QQ + q] = cost;
    }
}

// ---------------------------------------------------------------------------
// Reference _lsa, degenerate-form-exact (rounds 5-10). New this round:
//   * Deferred duals: within a phase, scans/candidate evals only ever read
//     PHASE-START u/v (provable: pivot row is always the newest chain row,
//     never yet updated; unused columns' v never changes within a phase).
//     Chain dual updates collapse to one parallel phase-end correction
//     u[row_k] += S_T - S_join[k], v[col_k] -= S_T - S_join[k].
//   * Within-phase 'used' marking lives in per-thread registers (vfr),
//     reloaded once per phase; no vv array, no per-scan LDS of vf.
// Deltas / pivots / first-index tie-breaks bit-identical to the reference.
// ---------------------------------------------------------------------------
#define LSA_THREADS 256
#define NE 4          // ceil(900/256)

__device__ __forceinline__ int f32_key(float f) {
    int k = __float_as_int(f);
    return k ^ ((k >> 31) & 0x7fffffff);   // monotone signed-int key
}
__device__ __forceinline__ float f32_unkey(int k) {
    return __int_as_float(k ^ ((k >> 31) & 0x7fffffff));
}

__global__ void lsa_kernel(float* __restrict__ out) {
    __shared__ double v [QQ + 1];      // dual v (phase-start within phases)
    __shared__ float  vf[QQ + 1];      // fp32 mirror of v
    __shared__ double u [NP + 2];      // dual u (rows 1..32; u[0] dummy)
    __shared__ int    p [QQ + 1];      // column -> row (1-based; 0 = free)
    __shared__ int    chain_col[NP + 4];
    __shared__ double S_join[NP + 4];  // delta prefix-sum at join time
    __shared__ int    cand[QQ + 4];    // candidate column list
    __shared__ int    s_n, s_j0, s_done, s_L;
    __shared__ double s_S;             // cumulative delta this phase

    const int tid  = threadIdx.x;
    const int lane = tid & 31;
    const int wid  = tid >> 5;
    const int b    = blockIdx.x;

    const float* __restrict__ cs = g_cost + (size_t)b * NP * QQ;

    for (int j = tid; j <= QQ; j += LSA_THREADS) {
        v[j] = 0.0; vf[j] = 0.0f; p[j] = 0;
    }
    for (int i = tid; i <= NP + 1; i += LSA_THREADS) u[i] = 0.0;
    if (tid == 0) s_n = 0;
    __syncthreads();

    for (int i = 1; i <= NP; i++) {
        // phase-start: load fp32 dual mirror into registers
        float vfr[NE];
        #pragma unroll
        for (int k = 0; k < NE; k++) {
            int j = tid + 1 + k * LSA_THREADS;
            vfr[k] = (j <= QQ) ? vf[j] : 0.0f;
        }
        if (tid == 0) {
            p[0] = i;
            chain_col[0] = 0;   // virtual column 0 holds row i
            S_join[0] = 0.0;
            s_L = 1;
            s_j0 = 0;
            s_done = 0;
            s_S = 0.0;
        }
        __syncthreads();

        while (true) {
            const int    i0   = p[s_j0];
            const double ui0d = u[i0];          // phase-start value
            const float  ui0f = (float)ui0d;
            const float* crow = cs + (size_t)(i0 - 1) * QQ;

            // ---- fp32 scan; used cols have vfr = -1e30f -> never selected
            float c4[NE];
            float bestf = 1e30f;
            #pragma unroll
            for (int k = 0; k < NE; k++) {
                int j = tid + 1 + k * LSA_THREADS;
                float cf = 1e30f;
                if (j <= QQ)
                    cf = (__ldg(crow + (j - 1)) - ui0f) - vfr[k];
                c4[k] = cf;
                bestf = fminf(bestf, cf);
            }
            int wmink = __reduce_min_sync(0xffffffffu, f32_key(bestf));
            float minf = f32_unkey(wmink);
            float thresh = minf + fmaxf(1e-2f, 1e-5f * fabsf(minf));

            #pragma unroll
            for (int k = 0; k < NE; k++) {
                if (c4[k] <= thresh) {
                    int slot = atomicAdd(&s_n, 1);
                    cand[slot] = tid + 1 + k * LSA_THREADS;
                }
            }
            __syncthreads();

            // ---- warp 0: exact fp64 candidate eval + argmin + O(1) record
            if (wid == 0) {
                const int n = s_n;
                double bestv = 1e300;
                int    bestj = QQ + 1;
                for (int base = 0; base < n; base += 32) {
                    int idx = base + lane;
                    if (idx < n) {
                        int jj = cand[idx];
                        // EXACT reference expression on phase-start duals
                        double cur = ((double)__ldg(crow + (jj - 1)) - ui0d)
                                     - v[jj];
                        if (cur < bestv || (cur == bestv && jj < bestj)) {
                            bestv = cur; bestj = jj;
                        }
                    }
                }
                // lexicographic (val, idx) warp argmin via redux cascade
                long long sbits = __double_as_longlong(bestv);
                unsigned long long ukey = (sbits >= 0)
                    ? ((unsigned long long)sbits | 0x8000000000000000ULL)
                    : ~(unsigned long long)sbits;
                unsigned hi = (unsigned)(ukey >> 32);
                unsigned lo = (unsigned)ukey;
                unsigned hmin = __reduce_min_sync(0xffffffffu, hi);
                unsigned lmin = __reduce_min_sync(0xffffffffu,
                                    (hi == hmin) ? lo : 0xffffffffu);
                int jmin = __reduce_min_sync(0xffffffffu,
                                (hi == hmin && lo == lmin) ? bestj
                                                           : 0x7fffffff);
                if (lane == 0) {
                    unsigned long long ukmin =
                        ((unsigned long long)hmin << 32) | lmin;
                    long long rbits = (ukmin & 0x8000000000000000ULL)
                        ? (long long)(ukmin ^ 0x8000000000000000ULL)
                        : ~(long long)ukmin;
                    const double delta = __longlong_as_double(rbits);
                    const int L = s_L;
                    double Snew = s_S + delta;
                    s_S = Snew;
                    chain_col[L] = jmin;
                    S_join[L] = Snew;
                    s_L = L + 1;
                    s_j0 = jmin;
                    s_n = 0;
                    s_done = (p[jmin] == 0) ? 1 : 0;
                }
            }
            __syncthreads();

            // mark the new pivot column used in its owner thread's registers
            {
                int idx = s_j0 - 1 - tid;
                if (idx >= 0 && (idx & (LSA_THREADS - 1)) == 0) {
                    int k = idx / LSA_THREADS;
                    if (k < NE) vfr[k] = -1e30f;
                }
            }
            if (s_done) break;
        }

        // ---- phase end (warp 0): deferred dual corrections + augment.
        // Chain cols distinct; rows distinct (matching); only the final
        // (free) element has row 0 and its correction is exactly 0.0.
        if (wid == 0) {
            const int L = s_L;         // <= 33
            const double ST = s_S;
            int k1 = lane, k2 = lane + 32;
            int col1 = (k1 < L) ? chain_col[k1] : -1;
            int col2 = (k2 < L) ? chain_col[k2] : -1;
            int row1 = (col1 >= 0) ? p[col1] : 0;
            int row2 = (col2 >= 0) ? p[col2] : 0;
            int prow1 = (k1 >= 1 && k1 < L) ? p[chain_col[k1 - 1]] : 0;
            int prow2 = (k2 >= 1 && k2 < L) ? p[chain_col[k2 - 1]] : 0;
            __syncwarp();
            if (col1 >= 0) {
                double corr = ST - S_join[k1];
                u[row1] += corr;
                if (col1 > 0) {
                    double nv = v[col1] - corr;
                    v[col1] = nv; vf[col1] = (float)nv;
                }
                if (k1 >= 1) p[col1] = prow1;
            }
            if (col2 >= 0) {
                double corr = ST - S_join[k2];
                u[row2] += corr;
                if (col2 > 0) {
                    double nv = v[col2] - corr;
                    v[col2] = nv; vf[col2] = (float)nv;
                }
                if (k2 >= 1) p[col2] = prow2;
            }
        }
        __syncthreads();
    }

    // write this block's 32-column output stripe (zeros + assignment ones)
    for (int j = tid + 1; j <= QQ; j += LSA_THREADS) {
        int t = p[j] - 1;
        float4* dst = reinterpret_cast<float4*>(
            out + (size_t)(j - 1) * TT + b * NP);
        #pragma unroll
        for (int k = 0; k < NP / 4; k++) {
            float4 w = make_float4(0.f, 0.f, 0.f, 0.f);
            if (t >= 4 * k && t < 4 * k + 4)
                reinterpret_cast<float*>(&w)[t - 4 * k] = 1.0f;
            dst[k] = w;
        }
    }
}

// ---------------------------------------------------------------------------
extern "C" void kernel_launch(void* const* d_in, const int* in_sizes, int n_in,
                              void* d_out, int out_size) {
    const float* logits = (const float*)d_in[0];
    const float* pboxes = (const float*)d_in[1];
    const int*   labraw = (const int*)d_in[2];
    const float* tboxes = (const float*)d_in[3];
    float* out = (float*)d_out;

    dim3 g(BB, (QQ + 127) / 128);
    cost_kernel<<<g, 128>>>(logits, pboxes, labraw, tboxes);
    lsa_kernel<<<BB, LSA_THREADS>>>(out);
}

// round 16
// speedup vs baseline: 2.5593x; 1.0586x over previous
#include <cuda_runtime.h>

// Problem shape (fixed by the benchmark):
//   pred_logits: (16, 900, 92) f32
//   pred_boxes : (16, 900, 4)  f32
//   tgt_labels : (512,)        int32 OR int64 (JAX x64-dependent) -- handled
//   tgt_boxes  : (512, 4)      f32
//   n_targets  : scalar (= 32)
//   output     : (900, 512)    f32  (0/1 assignment)
#define BB 16
#define QQ 900
#define CC 92
#define NP 32
#define TT (BB*NP)

#define BAR_ARRIVE(id, n) asm volatile("bar.arrive %0, %1;" :: "r"(id), "r"(n) : "memory")
#define BAR_SYNC(id, n)   asm volatile("bar.sync %0, %1;"   :: "r"(id), "r"(n) : "memory")

// Per-block cost matrices, layout [b][t][q], fp32; widened to fp64 exactly at
// use (matches np.asarray(c, float64)).
__device__ float g_cost[(size_t)BB * NP * QQ];

// ---------------------------------------------------------------------------
// Build the 16 diagonal cost blocks: cost[b][t][q]
//   cost = 5 * L1(cxcywh) - softmax_prob[label] - 2 * GIoU(xyxy)
// Label dtype (int32 vs int64) detected per-block from the first 1024 bytes
// (in-bounds under both interpretations; labels < 92 so int64 high words = 0).
// ---------------------------------------------------------------------------
__global__ void cost_kernel(const float* __restrict__ logits,
                            const float* __restrict__ pboxes,
                            const int*   __restrict__ labraw,
                            const float* __restrict__ tboxes) {
    int b = blockIdx.x;
    __shared__ int    s_nz;
    __shared__ int    s_lab[NP];
    __shared__ float4 s_tb[NP];
    __shared__ float4 s_txy[NP];
    __shared__ float  s_tarea[NP];

    int tid = threadIdx.x;
    if (tid == 0) s_nz = 0;
    __syncthreads();
    if (labraw[2 * tid + 1] != 0) atomicOr(&s_nz, 1);   // tid < 128
    __syncthreads();
    bool is_i64 = (s_nz == 0);

    if (tid < NP) {
        int g = b * NP + tid;
        int val = is_i64 ? labraw[2 * g] : labraw[g];
        s_lab[tid] = min(max(val, 0), CC - 1);
        float4 tb = reinterpret_cast<const float4*>(tboxes)[g];
        s_tb[tid] = tb;
        float x0 = tb.x - 0.5f * tb.z, y0 = tb.y - 0.5f * tb.w;
        float x1 = tb.x + 0.5f * tb.z, y1 = tb.y + 0.5f * tb.w;
        s_txy[tid] = make_float4(x0, y0, x1, y1);
        s_tarea[tid] = (x1 - x0) * (y1 - y0);
    }
    __syncthreads();

    int q = blockIdx.y * blockDim.x + tid;
    if (q >= QQ) return;

    const float*  lrow  = logits + ((size_t)b * QQ + q) * CC;
    const float4* lrow4 = reinterpret_cast<const float4*>(lrow);  // 92=23*4, 16B-aligned
    float mx = -1e30f;
    #pragma unroll
    for (int c4 = 0; c4 < CC / 4; c4++) {
        float4 t4 = __ldg(lrow4 + c4);
        mx = fmaxf(mx, fmaxf(fmaxf(t4.x, t4.y), fmaxf(t4.z, t4.w)));
    }
    float sum = 0.0f;
    #pragma unroll
    for (int c4 = 0; c4 < CC / 4; c4++) {
        float4 t4 = __ldg(lrow4 + c4);
        sum += expf(t4.x - mx) + expf(t4.y - mx) +
               expf(t4.z - mx) + expf(t4.w - mx);
    }
    float inv = 1.0f / sum;

    float4 pb = reinterpret_cast<const float4*>(pboxes)[b * QQ + q];
    float px0 = pb.x - 0.5f * pb.z, py0 = pb.y - 0.5f * pb.w;
    float px1 = pb.x + 0.5f * pb.z, py1 = pb.y + 0.5f * pb.w;
    float parea = (px1 - px0) * (py1 - py0);

    #pragma unroll 8
    for (int t = 0; t < NP; t++) {
        float prob = expf(__ldg(lrow + s_lab[t]) - mx) * inv;
        float4 tb = s_tb[t];
        float l1 = fabsf(pb.x - tb.x) + fabsf(pb.y - tb.y) +
                   fabsf(pb.z - tb.z) + fabsf(pb.w - tb.w);
        float4 txy = s_txy[t];
        float ltx = fmaxf(px0, txy.x), lty = fmaxf(py0, txy.y);
        float rbx = fminf(px1, txy.z), rby = fminf(py1, txy.w);
        float wi = fmaxf(rbx - ltx, 0.0f), hi = fmaxf(rby - lty, 0.0f);
        float inter = wi * hi;
        float uni = parea + s_tarea[t] - inter;
        float iou = inter / uni;
        float cx0 = fminf(px0, txy.x), cy0 = fminf(py0, txy.y);
        float cx1 = fmaxf(px1, txy.z), cy1 = fmaxf(py1, txy.w);
        float wc = fmaxf(cx1 - cx0, 0.0f), hc = fmaxf(cy1 - cy0, 0.0f);
        float areac = wc * hc;
        float giou = iou - (areac - uni) / areac;
        float cost = 5.0f * l1 - prob - 2.0f * giou;
        g_cost[((size_t)(b * NP + t)) * QQ + q] = cost;
    }
}

// ---------------------------------------------------------------------------
// Reference _lsa, degenerate-form-exact (rounds 5-11). New this round:
//   * Scan drops the row dual u[i0] (uniform offset -> argmin-invariant);
//     loop-top dependency is a single LDS of s_i0. Warp 0 keeps i0/u[i0] in
//     registers; the exact fp64 candidate eval keeps the FULL reference
//     expression ((double)c - u[i0]) - v[j], so deltas/pivots/tie-breaks are
//     bit-identical.
//   * Producer-consumer barriers: scanners bar.arrive on named barrier 1 and
//     wait once at the block barrier; warp 0 bar.syncs barrier 1, computes
//     the pivot, and releases -> one full round-trip per iteration.
//   * used-marking in per-thread register slots via broadcast s_jmin.
// ---------------------------------------------------------------------------
#define LSA_THREADS 256
#define NE 4          // ceil(900/256)

__device__ __forceinline__ int f32_key(float f) {
    int k = __float_as_int(f);
    return k ^ ((k >> 31) & 0x7fffffff);   // monotone signed-int key
}
__device__ __forceinline__ float f32_unkey(int k) {
    return __int_as_float(k ^ ((k >> 31) & 0x7fffffff));
}

__global__ void lsa_kernel(float* __restrict__ out) {
    __shared__ double v [QQ + 1];      // dual v (phase-start within phases)
    __shared__ float  vf[QQ + 1];      // fp32 mirror of v
    __shared__ double u [NP + 2];      // dual u (rows 1..32; u[0] dummy)
    __shared__ int    p [QQ + 1];      // column -> row (1-based; 0 = free)
    __shared__ int    chain_col[NP + 4];
    __shared__ double S_join[NP + 4];  // delta prefix-sum at join time
    __shared__ int    cand[QQ + 4];    // candidate column list
    __shared__ int    s_n, s_i0, s_jmin;

    const int tid  = threadIdx.x;
    const int lane = tid & 31;
    const int wid  = tid >> 5;
    const int b    = blockIdx.x;

    const float* __restrict__ cs = g_cost + (size_t)b * NP * QQ;

    for (int j = tid; j <= QQ; j += LSA_THREADS) {
        v[j] = 0.0; vf[j] = 0.0f; p[j] = 0;
    }
    for (int i = tid; i <= NP + 1; i += LSA_THREADS) u[i] = 0.0;
    if (tid == 0) s_n = 0;
    __syncthreads();

    for (int i = 1; i <= NP; i++) {
        // phase-start: load fp32 dual mirror into registers
        float vfr[NE];
        #pragma unroll
        for (int k = 0; k < NE; k++) {
            int j = tid + 1 + k * LSA_THREADS;
            vfr[k] = (j <= QQ) ? vf[j] : -1e30f;   // invalid slots excluded
        }
        if (tid == 0) {
            p[0] = i;
            chain_col[0] = 0;   // virtual column 0 holds row i
            S_join[0] = 0.0;
            s_i0 = i;
            s_jmin = 0;
        }
        // warp0 per-phase register state
        int    i0r   = i;
        double ui0dr = u[i];        // phase-start value (stable in phase)
        double S     = 0.0;
        int    Lr    = 1;
        __syncthreads();

        while (true) {
            const int jm = s_jmin;
            if (jm > 0) {           // mark previous pivot used (owner thread)
                #pragma unroll
                for (int k = 0; k < NE; k++)
                    if (jm == tid + 1 + k * LSA_THREADS) vfr[k] = -1e30f;
            }
            const int i0s = s_i0;
            if (i0s == 0) break;    // phase done (all warps together)

            const float* crow = cs + (size_t)(i0s - 1) * QQ;

            // ---- fp32 scan of key = c - vf[j]  (u[i0] offset dropped:
            // argmin-invariant). Used/invalid slots have vfr = -1e30f.
            float c4[NE];
            float bestf = 1e30f;
            #pragma unroll
            for (int k = 0; k < NE; k++) {
                int j = tid + 1 + k * LSA_THREADS;
                float cf = 1e30f;
                if (j <= QQ)
                    cf = __ldg(crow + (j - 1)) - vfr[k];
                c4[k] = cf;
                bestf = fminf(bestf, cf);
            }
            int wmink = __reduce_min_sync(0xffffffffu, f32_key(bestf));
            float minf = f32_unkey(wmink);
            float thresh = minf + fmaxf(1e-2f, 1e-5f * fabsf(minf));

            #pragma unroll
            for (int k = 0; k < NE; k++) {
                if (c4[k] <= thresh) {
                    int slot = atomicAdd(&s_n, 1);
                    cand[slot] = tid + 1 + k * LSA_THREADS;
                }
            }

            if (wid != 0) {
                BAR_ARRIVE(1, LSA_THREADS);   // non-blocking hand-off
                __syncthreads();               // wait for pivot publication
            } else {
                BAR_SYNC(1, LSA_THREADS);      // collect all candidates
                // ---- exact fp64 candidate eval (full reference expression)
                const int n = s_n;
                const float* crow0 = cs + (size_t)(i0r - 1) * QQ;
                double bestv = 1e300;
                int    bestj = QQ + 1;
                for (int base = 0; base < n; base += 32) {
                    int idx = base + lane;
                    if (idx < n) {
                        int jj = cand[idx];
                        double cur = ((double)__ldg(crow0 + (jj - 1)) - ui0dr)
                                     - v[jj];
                        if (cur < bestv || (cur == bestv && jj < bestj)) {
                            bestv = cur; bestj = jj;
                        }
                    }
                }
                // lexicographic (val, idx) warp argmin via redux cascade
                long long sbits = __double_as_longlong(bestv);
                unsigned long long ukey = (sbits >= 0)
                    ? ((unsigned long long)sbits | 0x8000000000000000ULL)
                    : ~(unsigned long long)sbits;
                unsigned hi = (unsigned)(ukey >> 32);
                unsigned lo = (unsigned)ukey;
                unsigned hmin = __reduce_min_sync(0xffffffffu, hi);
                unsigned lmin = __reduce_min_sync(0xffffffffu,
                                    (hi == hmin) ? lo : 0xffffffffu);
                int jmin = __reduce_min_sync(0xffffffffu,
                                (hi == hmin && lo == lmin) ? bestj
                                                           : 0x7fffffff);
                unsigned long long ukmin =
                    ((unsigned long long)hmin << 32) | lmin;
                long long rbits = (ukmin & 0x8000000000000000ULL)
                    ? (long long)(ukmin ^ 0x8000000000000000ULL)
                    : ~(long long)ukmin;
                const double delta = __longlong_as_double(rbits);

                S += delta;
                int rn = 0;
                if (lane == 0) {
                    rn = p[jmin];
                    chain_col[Lr] = jmin;
                    S_join[Lr] = S;
                    s_jmin = jmin;
                    s_i0 = rn;      // 0 -> phase done
                    s_n = 0;
                }
                rn = __shfl_sync(0xffffffffu, rn, 0);
                Lr += 1;
                i0r = rn;
                if (rn > 0) ui0dr = u[rn];   // phase-start value (LDS bcast)
                __syncthreads();
            }
        }

        // ---- phase end (warp 0): deferred dual corrections + augment.
        // Chain cols distinct; rows distinct (matching); final free element
        // has p[col]=0 -> row 0 (dummy u[0]) and correction 0.
        if (wid == 0) {
            const int L = Lr;          // <= 33
            const double ST = S;
            int k1 = lane, k2 = lane + 32;
            int col1 = (k1 < L) ? chain_col[k1] : -1;
            int col2 = (k2 < L) ? chain_col[k2] : -1;
            int row1 = (col1 >= 0) ? p[col1] : 0;
            int row2 = (col2 >= 0) ? p[col2] : 0;
            int prow1 = (k1 >= 1 && k1 < L) ? p[chain_col[k1 - 1]] : 0;
            int prow2 = (k2 >= 1 && k2 < L) ? p[chain_col[k2 - 1]] : 0;
            __syncwarp();
            if (col1 >= 0) {
                double corr = ST - S_join[k1];
                u[row1] += corr;
                if (col1 > 0) {
                    double nv = v[col1] - corr;
                    v[col1] = nv; vf[col1] = (float)nv;
                }
                if (k1 >= 1) p[col1] = prow1;
            }
            if (col2 >= 0) {
                double corr = ST - S_join[k2];
                u[row2] += corr;
                if (col2 > 0) {
                    double nv = v[col2] - corr;
                    v[col2] = nv; vf[col2] = (float)nv;
                }
                if (k2 >= 1) p[col2] = prow2;
            }
        }
        __syncthreads();
    }

    // write this block's 32-column output stripe (zeros + assignment ones)
    for (int j = tid + 1; j <= QQ; j += LSA_THREADS) {
        int t = p[j] - 1;
        float4* dst = reinterpret_cast<float4*>(
            out + (size_t)(j - 1) * TT + b * NP);
        #pragma unroll
        for (int k = 0; k < NP / 4; k++) {
            float4 w = make_float4(0.f, 0.f, 0.f, 0.f);
            if (t >= 4 * k && t < 4 * k + 4)
                reinterpret_cast<float*>(&w)[t - 4 * k] = 1.0f;
            dst[k] = w;
        }
    }
}

// ---------------------------------------------------------------------------
extern "C" void kernel_launch(void* const* d_in, const int* in_sizes, int n_in,
                              void* d_out, int out_size) {
    const float* logits = (const float*)d_in[0];
    const float* pboxes = (const float*)d_in[1];
    const int*   labraw = (const int*)d_in[2];
    const float* tboxes = (const float*)d_in[3];
    float* out = (float*)d_out;

    dim3 g(BB, (QQ + 127) / 128);
    cost_kernel<<<g, 128>>>(logits, pboxes, labraw, tboxes);
    lsa_kernel<<<BB, LSA_THREADS>>>(out);
}